// round 16
// baseline (speedup 1.0000x reference)
#include <cuda_runtime.h>
#include <cuda_fp16.h>

typedef unsigned int u32;
typedef unsigned long long u64;
typedef unsigned short u16;

#define HID 128
#define NMAX 50000
#define EMAX 500000

// ---------------- device scratch ----------------
__device__ float g_agg[(size_t)NMAX * HID];
__device__ float g_inv[NMAX];
__device__ int   g_indeg[NMAX];
__device__ int   g_nperm[NMAX];
__device__ int   g_rank[NMAX];
__device__ int   g_nodeoff[NMAX];
__device__ int   g_nodecur[NMAX];
__device__ int   g_partial[256];
__device__ int   g_ncnt[8], g_noff[8], g_ncur[8];
__device__ u32   g_done1, g_done2, g_done3;
__device__ volatile u32 g_scanflag;
// sorted edge arrays (by level, then dst): packed (eattr<<32 | src), dst
__device__ u64   g_ese[EMAX];
__device__ int   g_edst[EMAX];
// fp16 image of h
__device__ u16   g_hf[(size_t)NMAX * HID];
// weight images, [n][k] row-major, single fp16
__device__ u16   g_w1h[16384], g_w2h[16384];
__device__ u16   g_u1h[32768], g_u2h[16384];
__device__ u16   g_pwh[16384];

// ---------------- helpers ----------------
static __device__ __forceinline__ u32 h2pack(float f0, float f1){
    __half2 h = __floats2half2_rn(f0, f1);
    return *(u32*)&h;
}
static __device__ __forceinline__ u32 s2u(const void* p){
    u32 a; asm("{ .reg .u64 t; cvta.to.shared.u64 t, %1; cvt.u32.u64 %0, t; }" : "=r"(a) : "l"(p));
    return a;
}

#define LDX4(r, a) \
    asm volatile("ldmatrix.sync.aligned.m8n8.x4.shared.b16 {%0,%1,%2,%3}, [%4];" \
        : "=r"((r)[0]), "=r"((r)[1]), "=r"((r)[2]), "=r"((r)[3]) : "r"(a))

#define MMAH(d, a, b0, b1) \
    asm("mma.sync.aligned.m16n8k16.row.col.f32.f16.f16.f32 " \
        "{%0,%1,%2,%3}, {%4,%5,%6,%7}, {%8,%9}, {%0,%1,%2,%3};" \
        : "+f"((d)[0]), "+f"((d)[1]), "+f"((d)[2]), "+f"((d)[3]) \
        : "r"((a)[0]), "r"((a)[1]), "r"((a)[2]), "r"((a)[3]), "r"(b0), "r"(b1))

#define PAIR_BAR(id) asm volatile("bar.sync %0, 64;" :: "r"(id) : "memory")

// ---------------- init: zero scratch + build fp16 weight images ----------------
__global__ void k_init(int nagg, int N, const float* __restrict__ mw1, const float* __restrict__ mw2,
                       const float* __restrict__ uw1, const float* __restrict__ uw2,
                       const float* __restrict__ pw){
    int i  = blockIdx.x * blockDim.x + threadIdx.x;
    int st = gridDim.x * blockDim.x;
    for (int j = i; j < nagg; j += st) g_agg[j] = 0.f;
    for (int j = i; j < N;    j += st) g_indeg[j] = 0;
    if (i < 8) g_ncnt[i] = 0;
    for (int idx = i; idx < 98304; idx += st){
        const float* W; u16 *H; int n, k, kdim;
        if (idx < 32768){
            int mtx = idx >> 14, rem = idx & 16383;
            n = rem >> 7; k = rem & 127; kdim = 128;
            W = mtx ? mw2 : mw1; H = mtx ? g_w2h : g_w1h;
        } else if (idx < 65536){
            int j = idx - 32768;
            n = j >> 8; k = j & 255; kdim = 256;
            W = uw1; H = g_u1h;
        } else if (idx < 81920){
            int j = idx - 65536;
            n = j >> 7; k = j & 127; kdim = 128;
            W = uw2; H = g_u2h;
        } else {
            int j = idx - 81920;
            n = j >> 7; k = j & 127; kdim = 128;
            W = pw; H = g_pwh;
        }
        float v = W[k * HID + n];
        __half hh = __float2half_rn(v);
        H[n * kdim + k] = *(u16*)&hh;
    }
}

// ---------------- count (+ fused level scan in last block) ----------------
__global__ void k_count(const int* __restrict__ ei, const int* __restrict__ depth, int N, int E){
    __shared__ int scnt[8];
    int t = threadIdx.x;
    if (t < 8) scnt[t] = 0;
    __syncthreads();
    int i = blockIdx.x * blockDim.x + t;
    if (i < E) atomicAdd(&g_indeg[ei[E + i]], 1);
    if (i < N) atomicAdd(&scnt[depth[i]], 1);
    __syncthreads();
    if (t < 8 && scnt[t]) atomicAdd(&g_ncnt[t], scnt[t]);
    __syncthreads();
    if (t == 0){
        __threadfence();
        u32 old = atomicAdd(&g_done1, 1);
        if (old == gridDim.x - 1){
            g_done1 = 0;
            int n = 0;
            #pragma unroll
            for (int d = 0; d < 8; ++d){
                int c = atomicAdd(&g_ncnt[d], 0);
                g_noff[d] = n; g_ncur[d] = n; n += c;
            }
        }
    }
}

__global__ void k_snodes(const int* __restrict__ depth, int N){
    __shared__ int scnt[8], sbase[8];
    int t = threadIdx.x;
    if (t < 8) scnt[t] = 0;
    __syncthreads();
    int i = blockIdx.x * blockDim.x + t;
    int d = 0, pl = 0;
    if (i < N){ d = depth[i]; pl = atomicAdd(&scnt[d], 1); }
    __syncthreads();
    if (t < 8) sbase[t] = scnt[t] ? atomicAdd(&g_ncur[t], scnt[t]) : 0;
    __syncthreads();
    if (i < N){
        int pos = sbase[d] + pl;
        g_nperm[pos] = i;
        g_rank[i] = pos;
        int c = g_indeg[i];
        g_inv[i] = 1.0f / (float)(c > 0 ? c : 1);
    }
}

// fused 3-phase scan, single kernel (256 co-resident blocks, spin between phases)
__global__ void k_escan(int N){
    __shared__ int sh[256];
    __shared__ int slast;
    int chunk = (N + 255) / 256;
    int t = threadIdx.x;
    int i = blockIdx.x * chunk + t;
    int orig = 0;
    if (t < chunk && i < N) orig = g_indeg[g_nperm[i]];
    // phase 1: block sum
    sh[t] = orig; __syncthreads();
    for (int s = 128; s > 0; s >>= 1){
        if (t < s) sh[t] += sh[t + s];
        __syncthreads();
    }
    if (t == 0){
        g_partial[blockIdx.x] = sh[0];
        __threadfence();
        u32 old = atomicAdd(&g_done2, 1);
        slast = (old == gridDim.x - 1) ? 1 : 0;
        if (slast) g_done2 = 0;
    }
    __syncthreads();
    // phase 2: last block scans partials, raises flag
    if (slast){
        __threadfence();
        int po = g_partial[t];
        sh[t] = po; __syncthreads();
        for (int s = 1; s < 256; s <<= 1){
            int vv = (t >= s) ? sh[t - s] : 0;
            __syncthreads();
            sh[t] += vv;
            __syncthreads();
        }
        g_partial[t] = sh[t] - po;
        __threadfence();
        if (t == 0) g_scanflag = 1;
    }
    // all blocks wait for flag
    if (t == 0){
        while (g_scanflag == 0) __nanosleep(64);
    }
    __syncthreads();
    __threadfence();
    // phase 3: per-chunk inclusive scan + write offsets
    sh[t] = orig; __syncthreads();
    for (int s = 1; s < 256; s <<= 1){
        int v = (t >= s) ? sh[t - s] : 0;
        __syncthreads();
        sh[t] += v;
        __syncthreads();
    }
    if (t < chunk && i < N){
        int excl = g_partial[blockIdx.x] + sh[t] - orig;
        g_nodeoff[i] = excl;
        g_nodecur[i] = excl;
    }
    // reset flag after all blocks done
    __syncthreads();
    if (t == 0){
        __threadfence();
        u32 old = atomicAdd(&g_done3, 1);
        if (old == gridDim.x - 1){ g_done3 = 0; g_scanflag = 0; }
    }
}

__global__ void k_sedges(const int* __restrict__ ei, const float* __restrict__ eattr, int E){
    int e = blockIdx.x * blockDim.x + threadIdx.x;
    if (e < E){
        int dst = ei[E + e];
        int pos = atomicAdd(&g_nodecur[g_rank[dst]], 1);
        u32 sb = (u32)ei[e];
        u32 ab = __float_as_uint(eattr[e]);
        g_ese[pos] = ((u64)ab << 32) | (u64)sb;
        g_edst[pos] = dst;
    }
}

// ---------------- projection: HMMA fp16, warp-owns-rows ----------------
#define PW_OFF 34816
#define PMISC  69632
#define SMEM_PROJ (PMISC + 512)
__global__ __launch_bounds__(256, 2) void k_proj(const float* __restrict__ x, const float* __restrict__ pb,
                                                 float* __restrict__ h, int N){
    extern __shared__ char smc[];
    u32 smb = s2u(smc);
    int tid = threadIdx.x, wid = tid >> 5, lane = tid & 31;
    float* bs = (float*)(smc + PMISC);

    int ntiles = (N + 127) >> 7;
    if (blockIdx.x >= ntiles) return;

    for (int i = tid; i < 2048; i += 256){
        int n = i >> 4, kc = i & 15;
        *(uint4*)(smc + PW_OFF + (u32)n * 272 + (u32)kc * 16) = ((const uint4*)g_pwh)[i];
    }
    if (tid < 128) bs[tid] = pb[tid];
    __syncthreads();

    u32 afrag = smb + (u32)(wid * 16 + (lane & 15)) * 272 + (u32)((lane >> 4) << 4);
    int ra = wid * 16 + (lane >> 2);
    int rb = ra + 8;
    u32 lanemap = (u32)(((lane >> 4) << 3) + (lane & 7)) * 272 + (u32)(((lane >> 3) & 1) << 4);

    for (int t = blockIdx.x; t < ntiles; t += gridDim.x){
        {
            int m = tid >> 1, q = tid & 1;
            int row = t * 128 + m;
            const float4* xr = (const float4*)(x + (size_t)(row < N ? row : 0) * HID) + q * 16;
            #pragma unroll
            for (int j = 0; j < 8; ++j){
                float4 v0 = xr[2*j], v1 = xr[2*j + 1];
                uint4 pv;
                pv.x = h2pack(v0.x, v0.y);
                pv.y = h2pack(v0.z, v0.w);
                pv.z = h2pack(v1.x, v1.y);
                pv.w = h2pack(v1.z, v1.w);
                *(uint4*)(smc + (u32)m * 272 + (u32)(q * 8 + j) * 16) = pv;
            }
        }
        __syncthreads();

        u32 a[8][4];
        #pragma unroll
        for (int kc = 0; kc < 8; ++kc) LDX4(a[kc], afrag + kc * 32);
        __syncwarp();

        u32 wb0 = smb + PW_OFF + lanemap;
        int rga = t * 128 + ra, rgb = t * 128 + rb;
        #pragma unroll
        for (int np = 0; np < 8; ++np){
            float aH0[4] = {0,0,0,0}, aH1[4] = {0,0,0,0};
            u32 wb = wb0 + (u32)np * 16 * 272;
            #pragma unroll
            for (int kc = 0; kc < 8; ++kc){
                u32 bh[4];
                LDX4(bh, wb + kc * 32);
                MMAH(aH0, a[kc], bh[0], bh[1]);
                MMAH(aH1, a[kc], bh[2], bh[3]);
            }
            #pragma unroll
            for (int nch = 0; nch < 2; ++nch){
                const float* H = nch ? aH1 : aH0;
                int c = np * 16 + nch * 8 + 2 * (lane & 3);
                float bb0 = bs[c], bb1 = bs[c+1];
                float v0 = H[0] + bb0, v1 = H[1] + bb1;
                if (rga < N){
                    *(float2*)(h + (size_t)rga * HID + c) = make_float2(v0, v1);
                    *(u32*)(&g_hf[(size_t)rga * HID + c]) = h2pack(v0, v1);
                }
                v0 = H[2] + bb0; v1 = H[3] + bb1;
                if (rgb < N){
                    *(float2*)(h + (size_t)rgb * HID + c) = make_float2(v0, v1);
                    *(u32*)(&g_hf[(size_t)rgb * HID + c]) = h2pack(v0, v1);
                }
            }
        }
        __syncthreads();
    }
}

// ---------------- message MLP: HMMA fp16, 512 thr, warp-pair split, 2 blocks/SM ----------------
#define MW1OFF 34816
#define MW2OFF 69632
#define MSDOFF 104448
#define SMEM_MSG (MSDOFF + 2560)

__global__ __launch_bounds__(512, 2) void k_msg(const float* __restrict__ mw1, const float* __restrict__ mb1,
                                                const float* __restrict__ mb2, int N, int E, int lvl){
    extern __shared__ char smc[];
    u32 smb = s2u(smc);
    int tid = threadIdx.x, wid = tid >> 5, lane = tid & 31;

    int*   sdst = (int*)  (smc + MSDOFF);
    float* seat = (float*)(smc + MSDOFF + 512);
    float* b1s  = (float*)(smc + MSDOFF + 1024);
    float* b2s  = (float*)(smc + MSDOFF + 1536);
    float* wls  = (float*)(smc + MSDOFF + 2048);

    int b0 = g_noff[lvl];
    int ncount = g_ncnt[lvl];
    int b1 = b0 + ncount;
    int base = (b0 < N) ? g_nodeoff[b0] : E;
    int eend = (b1 < N) ? g_nodeoff[b1] : E;
    int cnt = eend - base;
    int ntiles = (cnt + 127) >> 7;
    if ((int)blockIdx.x >= ntiles) return;

    for (int i = tid; i < 2048; i += 512){
        int n = i >> 4, kc = i & 15;
        u32 off = (u32)n * 272 + (u32)kc * 16;
        *(uint4*)(smc + MW1OFF + off) = ((const uint4*)g_w1h)[i];
        *(uint4*)(smc + MW2OFF + off) = ((const uint4*)g_w2h)[i];
    }
    if (tid < 128){
        b1s[tid] = mb1[tid];
        b2s[tid] = mb2[tid];
        wls[tid] = mw1[128 * HID + tid];
    }
    __syncthreads();

    int rgrp = wid >> 1, nh = wid & 1;
    u32 afrag = smb + (u32)(rgrp * 16 + (lane & 15)) * 272 + (u32)((lane >> 4) << 4);
    int ra = rgrp * 16 + (lane >> 2);
    int rb = ra + 8;
    u32 lanemap = (u32)(((lane >> 4) << 3) + (lane & 7)) * 272 + (u32)(((lane >> 3) & 1) << 4);

    for (int t = blockIdx.x; t < ntiles; t += gridDim.x){
        {   // gather: 4 threads per row, 4 uint4 each; packed (src, eattr)
            int m = tid >> 2, q = tid & 3;
            int p = t * 128 + m;
            u64 se = (p < cnt) ? g_ese[base + p] : 0ull;
            int src = (int)(u32)se;
            if (q == 0){
                sdst[m] = (p < cnt) ? g_edst[base + p] : -1;
                seat[m] = __uint_as_float((u32)(se >> 32));
            }
            const uint4* hr = (const uint4*)(&g_hf[(size_t)src * HID]);
            #pragma unroll
            for (int j = 0; j < 4; ++j){
                int q4 = q * 4 + j;
                *(uint4*)(smc + (u32)m * 272 + (u32)q4 * 16) = hr[q4];
            }
        }
        __syncthreads();

        u32 a[8][4];
        #pragma unroll
        for (int kc = 0; kc < 8; ++kc) LDX4(a[kc], afrag + kc * 32);
        float ea_a = seat[ra], ea_b = seat[rb];
        PAIR_BAR(rgrp + 1);

        // layer 1: own col half
        u32 w1b = smb + MW1OFF + (u32)(nh * 64) * 272 + lanemap;
        #pragma unroll
        for (int np = 0; np < 4; ++np){
            float aH0[4] = {0,0,0,0}, aH1[4] = {0,0,0,0};
            u32 wb = w1b + (u32)np * 16 * 272;
            #pragma unroll
            for (int kc = 0; kc < 8; ++kc){
                u32 bh[4];
                LDX4(bh, wb + kc * 32);
                MMAH(aH0, a[kc], bh[0], bh[1]);
                MMAH(aH1, a[kc], bh[2], bh[3]);
            }
            #pragma unroll
            for (int nch = 0; nch < 2; ++nch){
                const float* H = nch ? aH1 : aH0;
                int c = nh * 64 + np * 16 + nch * 8 + 2 * (lane & 3);
                float w0 = wls[c], w1v = wls[c+1], bb0 = b1s[c], bb1 = b1s[c+1];
                float v0 = fmaxf(H[0] + bb0 + ea_a * w0,  0.f);
                float v1 = fmaxf(H[1] + bb1 + ea_a * w1v, 0.f);
                *(u32*)(smc + (u32)ra * 272 + (u32)c * 2) = h2pack(v0, v1);
                v0 = fmaxf(H[2] + bb0 + ea_b * w0,  0.f);
                v1 = fmaxf(H[3] + bb1 + ea_b * w1v, 0.f);
                *(u32*)(smc + (u32)rb * 272 + (u32)c * 2) = h2pack(v0, v1);
            }
        }
        PAIR_BAR(rgrp + 1);
        #pragma unroll
        for (int kc = 0; kc < 8; ++kc) LDX4(a[kc], afrag + kc * 32);
        PAIR_BAR(rgrp + 1);

        // layer 2: stage fp16 into own rows/cols
        u32 w2b = smb + MW2OFF + (u32)(nh * 64) * 272 + lanemap;
        #pragma unroll
        for (int np = 0; np < 4; ++np){
            float aH0[4] = {0,0,0,0}, aH1[4] = {0,0,0,0};
            u32 wb = w2b + (u32)np * 16 * 272;
            #pragma unroll
            for (int kc = 0; kc < 8; ++kc){
                u32 bh[4];
                LDX4(bh, wb + kc * 32);
                MMAH(aH0, a[kc], bh[0], bh[1]);
                MMAH(aH1, a[kc], bh[2], bh[3]);
            }
            #pragma unroll
            for (int nch = 0; nch < 2; ++nch){
                const float* H = nch ? aH1 : aH0;
                int c = nh * 64 + np * 16 + nch * 8 + 2 * (lane & 3);
                float bb0 = b2s[c], bb1 = b2s[c+1];
                float v0 = fmaxf(H[0] + bb0, 0.f);
                float v1 = fmaxf(H[1] + bb1, 0.f);
                *(u32*)(smc + (u32)ra * 272 + (u32)c * 2) = h2pack(v0, v1);
                v0 = fmaxf(H[2] + bb0, 0.f);
                v1 = fmaxf(H[3] + bb1, 0.f);
                *(u32*)(smc + (u32)rb * 272 + (u32)c * 2) = h2pack(v0, v1);
            }
        }
        __syncthreads();

        // segmented flush (dst-sorted rows): 8 groups x 16 rows, half2 cols
        {
            int c2 = tid & 63, g = tid >> 6;
            int r0 = g * 16;
            float run0 = 0.f, run1 = 0.f;
            int prev = sdst[r0];
            #pragma unroll
            for (int r = 0; r < 16; ++r){
                int rr = r0 + r;
                int d = sdst[rr];
                u32 pv = *(u32*)(smc + (u32)rr * 272 + (u32)c2 * 4);
                float2 fv = __half22float2(*(__half2*)&pv);
                if (d != prev){
                    if (prev >= 0){
                        atomicAdd(&g_agg[(size_t)prev * HID + 2*c2],     run0);
                        atomicAdd(&g_agg[(size_t)prev * HID + 2*c2 + 1], run1);
                    }
                    run0 = 0.f; run1 = 0.f;
                    prev = d;
                }
                run0 += fv.x; run1 += fv.y;
            }
            if (prev >= 0){
                atomicAdd(&g_agg[(size_t)prev * HID + 2*c2],     run0);
                atomicAdd(&g_agg[(size_t)prev * HID + 2*c2 + 1], run1);
            }
        }
        __syncthreads();
    }
}

// ---------------- fused node update: HMMA, 64-row tiles, 256 thr, full-chip ----------------
// SMEM: A [64][528] at 0 (33792); T [64][272] at 33792 (17408);
// U1 at 51200 (67584); U2 at 118784 (34816); misc at 153600
#define U_T   33792
#define U_W1  51200
#define U_W2  118784
#define U_MISC 153600
#define SMEM_UPD (U_MISC + 1536)

__global__ __launch_bounds__(256, 1) void k_upd(float* __restrict__ h, const float* __restrict__ ub1,
                                                const float* __restrict__ ub2, int lvl){
    extern __shared__ char smc[];
    u32 smb = s2u(smc);
    int tid = threadIdx.x, wid = tid >> 5, lane = tid & 31;
    int*   snode = (int*)(smc + U_MISC);
    float* b1s   = (float*)(smc + U_MISC + 512);
    float* b2s   = (float*)(smc + U_MISC + 1024);

    int cnt  = g_ncnt[lvl];
    int base = g_noff[lvl];
    int ntiles = (cnt + 63) >> 6;
    if ((int)blockIdx.x >= ntiles) return;

    for (int i = tid; i < 4096; i += 256){
        int n = i >> 5, kc = i & 31;
        *(uint4*)(smc + U_W1 + (u32)n * 528 + (u32)kc * 16) = ((const uint4*)g_u1h)[i];
    }
    for (int i = tid; i < 2048; i += 256){
        int n = i >> 4, kc = i & 15;
        *(uint4*)(smc + U_W2 + (u32)n * 272 + (u32)kc * 16) = ((const uint4*)g_u2h)[i];
    }
    if (tid < 128){ b1s[tid] = ub1[tid]; b2s[tid] = ub2[tid]; }
    __syncthreads();

    int rgrp = wid >> 1, nh = wid & 1;
    u32 afrag1 = smb + (u32)(rgrp * 16 + (lane & 15)) * 528 + (u32)((lane >> 4) << 4);
    u32 afrag2 = smb + U_T + (u32)(rgrp * 16 + (lane & 15)) * 272 + (u32)((lane >> 4) << 4);
    int ra = rgrp * 16 + (lane >> 2);
    int rb = ra + 8;
    u32 lanemap1 = (u32)(((lane >> 4) << 3) + (lane & 7)) * 528 + (u32)(((lane >> 3) & 1) << 4);
    u32 lanemap2 = (u32)(((lane >> 4) << 3) + (lane & 7)) * 272 + (u32)(((lane >> 3) & 1) << 4);

    for (int t = blockIdx.x; t < ntiles; t += gridDim.x){
        __syncthreads();
        {   // gather A = [h fp16 | agg*inv fp16], 64 rows, 4 thr/row
            int m = tid >> 2, q = tid & 3;
            int p = t * 64 + m;
            int v = (p < cnt) ? g_nperm[base + p] : 0;
            float inv = g_inv[v];
            if (q == 0) snode[m] = (p < cnt) ? v : -1;
            const uint4*  hr = (const uint4*)(&g_hf[(size_t)v * HID]);
            const float4* ar = (const float4*)(&g_agg[(size_t)v * HID]);
            #pragma unroll
            for (int j = 0; j < 4; ++j){
                int q4 = q * 4 + j;
                *(uint4*)(smc + (u32)m * 528 + (u32)q4 * 16) = hr[q4];
                float4 a0 = ar[2 * q4], a1 = ar[2 * q4 + 1];
                uint4 pv;
                pv.x = h2pack(a0.x * inv, a0.y * inv);
                pv.y = h2pack(a0.z * inv, a0.w * inv);
                pv.z = h2pack(a1.x * inv, a1.y * inv);
                pv.w = h2pack(a1.z * inv, a1.w * inv);
                *(uint4*)(smc + (u32)m * 528 + 256 + (u32)q4 * 16) = pv;
            }
        }
        __syncthreads();

        // layer 1 (K = 256)
        u32 a1[16][4];
        #pragma unroll
        for (int kc = 0; kc < 16; ++kc) LDX4(a1[kc], afrag1 + kc * 32);

        u32 w1b = smb + U_W1 + (u32)(nh * 64) * 528 + lanemap1;
        #pragma unroll
        for (int np = 0; np < 4; ++np){
            float aH0[4] = {0,0,0,0}, aH1[4] = {0,0,0,0};
            u32 wb = w1b + (u32)np * 16 * 528;
            #pragma unroll
            for (int kc = 0; kc < 16; ++kc){
                u32 bh[4];
                LDX4(bh, wb + kc * 32);
                MMAH(aH0, a1[kc], bh[0], bh[1]);
                MMAH(aH1, a1[kc], bh[2], bh[3]);
            }
            #pragma unroll
            for (int nch = 0; nch < 2; ++nch){
                const float* H = nch ? aH1 : aH0;
                int c = nh * 64 + np * 16 + nch * 8 + 2 * (lane & 3);
                float bb0 = b1s[c], bb1 = b1s[c+1];
                float v0 = fmaxf(H[0] + bb0, 0.f);
                float v1 = fmaxf(H[1] + bb1, 0.f);
                *(u32*)(smc + U_T + (u32)ra * 272 + (u32)c * 2) = h2pack(v0, v1);
                v0 = fmaxf(H[2] + bb0, 0.f);
                v1 = fmaxf(H[3] + bb1, 0.f);
                *(u32*)(smc + U_T + (u32)rb * 272 + (u32)c * 2) = h2pack(v0, v1);
            }
        }
        PAIR_BAR(rgrp + 1);

        // layer 2 (K = 128)
        u32 a2[8][4];
        #pragma unroll
        for (int kc = 0; kc < 8; ++kc) LDX4(a2[kc], afrag2 + kc * 32);

        u32 w2b = smb + U_W2 + (u32)(nh * 64) * 272 + lanemap2;
        int na = snode[ra], nb = snode[rb];
        #pragma unroll
        for (int np = 0; np < 4; ++np){
            float aH0[4] = {0,0,0,0}, aH1[4] = {0,0,0,0};
            u32 wb = w2b + (u32)np * 16 * 272;
            #pragma unroll
            for (int kc = 0; kc < 8; ++kc){
                u32 bh[4];
                LDX4(bh, wb + kc * 32);
                MMAH(aH0, a2[kc], bh[0], bh[1]);
                MMAH(aH1, a2[kc], bh[2], bh[3]);
            }
            #pragma unroll
            for (int nch = 0; nch < 2; ++nch){
                const float* H = nch ? aH1 : aH0;
                int c = nh * 64 + np * 16 + nch * 8 + 2 * (lane & 3);
                float bb0 = b2s[c], bb1 = b2s[c+1];
                float v0 = fmaxf(H[0] + bb0, 0.f);
                float v1 = fmaxf(H[1] + bb1, 0.f);
                if (na >= 0){
                    *(float2*)(h + (size_t)na * HID + c) = make_float2(v0, v1);
                    *(u32*)(&g_hf[(size_t)na * HID + c]) = h2pack(v0, v1);
                }
                v0 = fmaxf(H[2] + bb0, 0.f);
                v1 = fmaxf(H[3] + bb1, 0.f);
                if (nb >= 0){
                    *(float2*)(h + (size_t)nb * HID + c) = make_float2(v0, v1);
                    *(u32*)(&g_hf[(size_t)nb * HID + c]) = h2pack(v0, v1);
                }
            }
        }
    }
}

// ---------------- host launch ----------------
extern "C" void kernel_launch(void* const* d_in, const int* in_sizes, int n_in,
                              void* d_out, int out_size){
    const float* x     = (const float*)d_in[0];
    const int*   ei    = (const int*)  d_in[1];
    const float* eattr = (const float*)d_in[2];
    const int*   depth = (const int*)  d_in[3];
    const float* pw    = (const float*)d_in[4];
    const float* pb    = (const float*)d_in[5];
    const float* mw1   = (const float*)d_in[6];
    const float* mb1   = (const float*)d_in[7];
    const float* mw2   = (const float*)d_in[8];
    const float* mb2   = (const float*)d_in[9];
    const float* uw1   = (const float*)d_in[10];
    const float* ub1   = (const float*)d_in[11];
    const float* uw2   = (const float*)d_in[12];
    const float* ub2   = (const float*)d_in[13];
    float* h = (float*)d_out;

    int N = in_sizes[3];
    int E = in_sizes[2];

    static int sms = 0;
    if (sms == 0){
        cudaDeviceGetAttribute(&sms, cudaDevAttrMultiProcessorCount, 0);
        if (sms <= 0) sms = 148;
        cudaFuncSetAttribute(k_proj, cudaFuncAttributeMaxDynamicSharedMemorySize, SMEM_PROJ);
        cudaFuncSetAttribute(k_msg,  cudaFuncAttributeMaxDynamicSharedMemorySize, SMEM_MSG);
        cudaFuncSetAttribute(k_upd,  cudaFuncAttributeMaxDynamicSharedMemorySize, SMEM_UPD);
    }

    k_init<<<1024, 256>>>(N * HID, N, mw1, mw2, uw1, uw2, pw);

    int mx = (E > N) ? E : N;
    k_count<<<(mx + 255) / 256, 256>>>(ei, depth, N, E);
    k_snodes<<<(N + 255) / 256, 256>>>(depth, N);
    k_escan<<<256, 256>>>(N);
    k_sedges<<<(E + 255) / 256, 256>>>(ei, eattr, E);

    k_proj<<<2 * sms, 256, SMEM_PROJ>>>(x, pb, h, N);

    for (int d = 1; d <= 4; ++d){
        k_msg<<<2 * sms, 512, SMEM_MSG>>>(mw1, mb1, mb2, N, E, d);
        k_upd<<<sms, 256, SMEM_UPD>>>(h, ub1, ub2, d);
    }
}

// round 17
// speedup vs baseline: 1.0327x; 1.0327x over previous
#include <cuda_runtime.h>
#include <cuda_fp16.h>

typedef unsigned int u32;
typedef unsigned long long u64;
typedef unsigned short u16;

#define HID 128
#define NMAX 50000
#define EMAX 500000

// ---------------- device scratch ----------------
__device__ float g_agg[(size_t)NMAX * HID];
__device__ float g_inv[NMAX];
__device__ int   g_indeg[NMAX];
__device__ int   g_nperm[NMAX];
__device__ int   g_nodecur[NMAX];      // per-node edge write cursor
__device__ int   g_ncnt[8], g_noff[8], g_ncur[8];
__device__ int   g_ecntl[8], g_eoffl[8], g_ecurl[8];
__device__ u32   g_done1;
// sorted edge arrays (grouped by level, contiguous per dst): packed (eattr<<32 | src), dst
__device__ u64   g_ese[EMAX];
__device__ int   g_edst[EMAX];
// fp16 image of h
__device__ u16   g_hf[(size_t)NMAX * HID];
// weight images, [n][k] row-major, single fp16
__device__ u16   g_w1h[16384], g_w2h[16384];
__device__ u16   g_u1h[32768], g_u2h[16384];
__device__ u16   g_pwh[16384];

// ---------------- helpers ----------------
static __device__ __forceinline__ u32 h2pack(float f0, float f1){
    __half2 h = __floats2half2_rn(f0, f1);
    return *(u32*)&h;
}
static __device__ __forceinline__ u32 s2u(const void* p){
    u32 a; asm("{ .reg .u64 t; cvta.to.shared.u64 t, %1; cvt.u32.u64 %0, t; }" : "=r"(a) : "l"(p));
    return a;
}

#define LDX4(r, a) \
    asm volatile("ldmatrix.sync.aligned.m8n8.x4.shared.b16 {%0,%1,%2,%3}, [%4];" \
        : "=r"((r)[0]), "=r"((r)[1]), "=r"((r)[2]), "=r"((r)[3]) : "r"(a))

#define MMAH(d, a, b0, b1) \
    asm("mma.sync.aligned.m16n8k16.row.col.f32.f16.f16.f32 " \
        "{%0,%1,%2,%3}, {%4,%5,%6,%7}, {%8,%9}, {%0,%1,%2,%3};" \
        : "+f"((d)[0]), "+f"((d)[1]), "+f"((d)[2]), "+f"((d)[3]) \
        : "r"((a)[0]), "r"((a)[1]), "r"((a)[2]), "r"((a)[3]), "r"(b0), "r"(b1))

#define PAIR_BAR(id) asm volatile("bar.sync %0, 64;" :: "r"(id) : "memory")

// ---------------- init: zero scratch + build fp16 weight images ----------------
__global__ void k_init(int nagg, int N, const float* __restrict__ mw1, const float* __restrict__ mw2,
                       const float* __restrict__ uw1, const float* __restrict__ uw2,
                       const float* __restrict__ pw){
    int i  = blockIdx.x * blockDim.x + threadIdx.x;
    int st = gridDim.x * blockDim.x;
    for (int j = i; j < nagg; j += st) g_agg[j] = 0.f;
    for (int j = i; j < N;    j += st) g_indeg[j] = 0;
    if (i < 8){ g_ncnt[i] = 0; g_ecntl[i] = 0; }
    for (int idx = i; idx < 98304; idx += st){
        const float* W; u16 *H; int n, k, kdim;
        if (idx < 32768){
            int mtx = idx >> 14, rem = idx & 16383;
            n = rem >> 7; k = rem & 127; kdim = 128;
            W = mtx ? mw2 : mw1; H = mtx ? g_w2h : g_w1h;
        } else if (idx < 65536){
            int j = idx - 32768;
            n = j >> 8; k = j & 255; kdim = 256;
            W = uw1; H = g_u1h;
        } else if (idx < 81920){
            int j = idx - 65536;
            n = j >> 7; k = j & 127; kdim = 128;
            W = uw2; H = g_u2h;
        } else {
            int j = idx - 81920;
            n = j >> 7; k = j & 127; kdim = 128;
            W = pw; H = g_pwh;
        }
        float v = W[k * HID + n];
        __half hh = __float2half_rn(v);
        H[n * kdim + k] = *(u16*)&hh;
    }
}

// ---------------- count nodes + edges per level (+ last-block base computation) ----------------
__global__ void k_count(const int* __restrict__ ei, const int* __restrict__ depth, int N, int E){
    __shared__ int scn[8], sce[8];
    int t = threadIdx.x;
    if (t < 8){ scn[t] = 0; sce[t] = 0; }
    __syncthreads();
    int i = blockIdx.x * blockDim.x + t;
    if (i < E){
        int dst = ei[E + i];
        atomicAdd(&g_indeg[dst], 1);
        atomicAdd(&sce[depth[dst]], 1);
    }
    if (i < N) atomicAdd(&scn[depth[i]], 1);
    __syncthreads();
    if (t < 8){
        if (scn[t]) atomicAdd(&g_ncnt[t], scn[t]);
        if (sce[t]) atomicAdd(&g_ecntl[t], sce[t]);
    }
    __syncthreads();
    if (t == 0){
        __threadfence();
        u32 old = atomicAdd(&g_done1, 1);
        if (old == gridDim.x - 1){
            g_done1 = 0;
            int n = 0, e = 0;
            #pragma unroll
            for (int d = 0; d < 8; ++d){
                int cn = atomicAdd(&g_ncnt[d], 0);
                int ce = atomicAdd(&g_ecntl[d], 0);
                g_noff[d] = n; g_ncur[d] = n; n += cn;
                g_eoffl[d] = e; g_ecurl[d] = e; e += ce;
            }
        }
    }
}

// ---------------- node placement + direct edge-range reservation ----------------
__global__ void k_snodes(const int* __restrict__ depth, int N){
    __shared__ int scnt[8], sdeg[8], sbase[8], sebase[8];
    int t = threadIdx.x;
    if (t < 8){ scnt[t] = 0; sdeg[t] = 0; }
    __syncthreads();
    int i = blockIdx.x * blockDim.x + t;
    int d = 0, pl = 0, pe = 0, deg = 0;
    if (i < N){
        d = depth[i];
        deg = g_indeg[i];
        pl = atomicAdd(&scnt[d], 1);
        pe = atomicAdd(&sdeg[d], deg);
    }
    __syncthreads();
    if (t < 8){
        sbase[t]  = scnt[t] ? atomicAdd(&g_ncur[t],  scnt[t]) : 0;
        sebase[t] = sdeg[t] ? atomicAdd(&g_ecurl[t], sdeg[t]) : 0;
    }
    __syncthreads();
    if (i < N){
        g_nperm[sbase[d] + pl] = i;
        g_nodecur[i] = sebase[d] + pe;
        g_inv[i] = 1.0f / (float)(deg > 0 ? deg : 1);
    }
}

__global__ void k_sedges(const int* __restrict__ ei, const float* __restrict__ eattr, int E){
    int e = blockIdx.x * blockDim.x + threadIdx.x;
    if (e < E){
        int dst = ei[E + e];
        int pos = atomicAdd(&g_nodecur[dst], 1);
        u32 sb = (u32)ei[e];
        u32 ab = __float_as_uint(eattr[e]);
        g_ese[pos] = ((u64)ab << 32) | (u64)sb;
        g_edst[pos] = dst;
    }
}

// ---------------- projection: HMMA fp16, warp-owns-rows ----------------
#define PW_OFF 34816
#define PMISC  69632
#define SMEM_PROJ (PMISC + 512)
__global__ __launch_bounds__(256, 2) void k_proj(const float* __restrict__ x, const float* __restrict__ pb,
                                                 float* __restrict__ h, int N){
    extern __shared__ char smc[];
    u32 smb = s2u(smc);
    int tid = threadIdx.x, wid = tid >> 5, lane = tid & 31;
    float* bs = (float*)(smc + PMISC);

    int ntiles = (N + 127) >> 7;
    if (blockIdx.x >= ntiles) return;

    for (int i = tid; i < 2048; i += 256){
        int n = i >> 4, kc = i & 15;
        *(uint4*)(smc + PW_OFF + (u32)n * 272 + (u32)kc * 16) = ((const uint4*)g_pwh)[i];
    }
    if (tid < 128) bs[tid] = pb[tid];
    __syncthreads();

    u32 afrag = smb + (u32)(wid * 16 + (lane & 15)) * 272 + (u32)((lane >> 4) << 4);
    int ra = wid * 16 + (lane >> 2);
    int rb = ra + 8;
    u32 lanemap = (u32)(((lane >> 4) << 3) + (lane & 7)) * 272 + (u32)(((lane >> 3) & 1) << 4);

    for (int t = blockIdx.x; t < ntiles; t += gridDim.x){
        {
            int m = tid >> 1, q = tid & 1;
            int row = t * 128 + m;
            const float4* xr = (const float4*)(x + (size_t)(row < N ? row : 0) * HID) + q * 16;
            #pragma unroll
            for (int j = 0; j < 8; ++j){
                float4 v0 = xr[2*j], v1 = xr[2*j + 1];
                uint4 pv;
                pv.x = h2pack(v0.x, v0.y);
                pv.y = h2pack(v0.z, v0.w);
                pv.z = h2pack(v1.x, v1.y);
                pv.w = h2pack(v1.z, v1.w);
                *(uint4*)(smc + (u32)m * 272 + (u32)(q * 8 + j) * 16) = pv;
            }
        }
        __syncthreads();

        u32 a[8][4];
        #pragma unroll
        for (int kc = 0; kc < 8; ++kc) LDX4(a[kc], afrag + kc * 32);
        __syncwarp();

        u32 wb0 = smb + PW_OFF + lanemap;
        int rga = t * 128 + ra, rgb = t * 128 + rb;
        #pragma unroll
        for (int np = 0; np < 8; ++np){
            float aH0[4] = {0,0,0,0}, aH1[4] = {0,0,0,0};
            u32 wb = wb0 + (u32)np * 16 * 272;
            #pragma unroll
            for (int kc = 0; kc < 8; ++kc){
                u32 bh[4];
                LDX4(bh, wb + kc * 32);
                MMAH(aH0, a[kc], bh[0], bh[1]);
                MMAH(aH1, a[kc], bh[2], bh[3]);
            }
            #pragma unroll
            for (int nch = 0; nch < 2; ++nch){
                const float* H = nch ? aH1 : aH0;
                int c = np * 16 + nch * 8 + 2 * (lane & 3);
                float bb0 = bs[c], bb1 = bs[c+1];
                float v0 = H[0] + bb0, v1 = H[1] + bb1;
                if (rga < N){
                    *(float2*)(h + (size_t)rga * HID + c) = make_float2(v0, v1);
                    *(u32*)(&g_hf[(size_t)rga * HID + c]) = h2pack(v0, v1);
                }
                v0 = H[2] + bb0; v1 = H[3] + bb1;
                if (rgb < N){
                    *(float2*)(h + (size_t)rgb * HID + c) = make_float2(v0, v1);
                    *(u32*)(&g_hf[(size_t)rgb * HID + c]) = h2pack(v0, v1);
                }
            }
        }
        __syncthreads();
    }
}

// ---------------- message MLP: HMMA fp16, 512 thr, warp-pair split, 2 blocks/SM ----------------
#define MW1OFF 34816
#define MW2OFF 69632
#define MSDOFF 104448
#define SMEM_MSG (MSDOFF + 2560)

__global__ __launch_bounds__(512, 2) void k_msg(const float* __restrict__ mw1, const float* __restrict__ mb1,
                                                const float* __restrict__ mb2, int lvl){
    extern __shared__ char smc[];
    u32 smb = s2u(smc);
    int tid = threadIdx.x, wid = tid >> 5, lane = tid & 31;

    int*   sdst = (int*)  (smc + MSDOFF);
    float* seat = (float*)(smc + MSDOFF + 512);
    float* b1s  = (float*)(smc + MSDOFF + 1024);
    float* b2s  = (float*)(smc + MSDOFF + 1536);
    float* wls  = (float*)(smc + MSDOFF + 2048);

    int base = g_eoffl[lvl];
    int cnt  = g_ecntl[lvl];
    int ntiles = (cnt + 127) >> 7;
    if ((int)blockIdx.x >= ntiles) return;

    for (int i = tid; i < 2048; i += 512){
        int n = i >> 4, kc = i & 15;
        u32 off = (u32)n * 272 + (u32)kc * 16;
        *(uint4*)(smc + MW1OFF + off) = ((const uint4*)g_w1h)[i];
        *(uint4*)(smc + MW2OFF + off) = ((const uint4*)g_w2h)[i];
    }
    if (tid < 128){
        b1s[tid] = mb1[tid];
        b2s[tid] = mb2[tid];
        wls[tid] = mw1[128 * HID + tid];
    }
    __syncthreads();

    int rgrp = wid >> 1, nh = wid & 1;
    u32 afrag = smb + (u32)(rgrp * 16 + (lane & 15)) * 272 + (u32)((lane >> 4) << 4);
    int ra = rgrp * 16 + (lane >> 2);
    int rb = ra + 8;
    u32 lanemap = (u32)(((lane >> 4) << 3) + (lane & 7)) * 272 + (u32)(((lane >> 3) & 1) << 4);

    for (int t = blockIdx.x; t < ntiles; t += gridDim.x){
        {   // gather: 4 threads per row, 4 uint4 each; packed (src, eattr)
            int m = tid >> 2, q = tid & 3;
            int p = t * 128 + m;
            u64 se = (p < cnt) ? g_ese[base + p] : 0ull;
            int src = (int)(u32)se;
            if (q == 0){
                sdst[m] = (p < cnt) ? g_edst[base + p] : -1;
                seat[m] = __uint_as_float((u32)(se >> 32));
            }
            const uint4* hr = (const uint4*)(&g_hf[(size_t)src * HID]);
            #pragma unroll
            for (int j = 0; j < 4; ++j){
                int q4 = q * 4 + j;
                *(uint4*)(smc + (u32)m * 272 + (u32)q4 * 16) = hr[q4];
            }
        }
        __syncthreads();

        u32 a[8][4];
        #pragma unroll
        for (int kc = 0; kc < 8; ++kc) LDX4(a[kc], afrag + kc * 32);
        float ea_a = seat[ra], ea_b = seat[rb];
        PAIR_BAR(rgrp + 1);

        // layer 1: own col half
        u32 w1b = smb + MW1OFF + (u32)(nh * 64) * 272 + lanemap;
        #pragma unroll
        for (int np = 0; np < 4; ++np){
            float aH0[4] = {0,0,0,0}, aH1[4] = {0,0,0,0};
            u32 wb = w1b + (u32)np * 16 * 272;
            #pragma unroll
            for (int kc = 0; kc < 8; ++kc){
                u32 bh[4];
                LDX4(bh, wb + kc * 32);
                MMAH(aH0, a[kc], bh[0], bh[1]);
                MMAH(aH1, a[kc], bh[2], bh[3]);
            }
            #pragma unroll
            for (int nch = 0; nch < 2; ++nch){
                const float* H = nch ? aH1 : aH0;
                int c = nh * 64 + np * 16 + nch * 8 + 2 * (lane & 3);
                float w0 = wls[c], w1v = wls[c+1], bb0 = b1s[c], bb1 = b1s[c+1];
                float v0 = fmaxf(H[0] + bb0 + ea_a * w0,  0.f);
                float v1 = fmaxf(H[1] + bb1 + ea_a * w1v, 0.f);
                *(u32*)(smc + (u32)ra * 272 + (u32)c * 2) = h2pack(v0, v1);
                v0 = fmaxf(H[2] + bb0 + ea_b * w0,  0.f);
                v1 = fmaxf(H[3] + bb1 + ea_b * w1v, 0.f);
                *(u32*)(smc + (u32)rb * 272 + (u32)c * 2) = h2pack(v0, v1);
            }
        }
        PAIR_BAR(rgrp + 1);
        #pragma unroll
        for (int kc = 0; kc < 8; ++kc) LDX4(a[kc], afrag + kc * 32);
        PAIR_BAR(rgrp + 1);

        // layer 2: stage fp16 into own rows/cols
        u32 w2b = smb + MW2OFF + (u32)(nh * 64) * 272 + lanemap;
        #pragma unroll
        for (int np = 0; np < 4; ++np){
            float aH0[4] = {0,0,0,0}, aH1[4] = {0,0,0,0};
            u32 wb = w2b + (u32)np * 16 * 272;
            #pragma unroll
            for (int kc = 0; kc < 8; ++kc){
                u32 bh[4];
                LDX4(bh, wb + kc * 32);
                MMAH(aH0, a[kc], bh[0], bh[1]);
                MMAH(aH1, a[kc], bh[2], bh[3]);
            }
            #pragma unroll
            for (int nch = 0; nch < 2; ++nch){
                const float* H = nch ? aH1 : aH0;
                int c = nh * 64 + np * 16 + nch * 8 + 2 * (lane & 3);
                float bb0 = b2s[c], bb1 = b2s[c+1];
                float v0 = fmaxf(H[0] + bb0, 0.f);
                float v1 = fmaxf(H[1] + bb1, 0.f);
                *(u32*)(smc + (u32)ra * 272 + (u32)c * 2) = h2pack(v0, v1);
                v0 = fmaxf(H[2] + bb0, 0.f);
                v1 = fmaxf(H[3] + bb1, 0.f);
                *(u32*)(smc + (u32)rb * 272 + (u32)c * 2) = h2pack(v0, v1);
            }
        }
        __syncthreads();

        // segmented flush (dst-grouped rows): 8 groups x 16 rows, half2 cols
        {
            int c2 = tid & 63, g = tid >> 6;
            int r0 = g * 16;
            float run0 = 0.f, run1 = 0.f;
            int prev = sdst[r0];
            #pragma unroll
            for (int r = 0; r < 16; ++r){
                int rr = r0 + r;
                int d = sdst[rr];
                u32 pv = *(u32*)(smc + (u32)rr * 272 + (u32)c2 * 4);
                float2 fv = __half22float2(*(__half2*)&pv);
                if (d != prev){
                    if (prev >= 0){
                        atomicAdd(&g_agg[(size_t)prev * HID + 2*c2],     run0);
                        atomicAdd(&g_agg[(size_t)prev * HID + 2*c2 + 1], run1);
                    }
                    run0 = 0.f; run1 = 0.f;
                    prev = d;
                }
                run0 += fv.x; run1 += fv.y;
            }
            if (prev >= 0){
                atomicAdd(&g_agg[(size_t)prev * HID + 2*c2],     run0);
                atomicAdd(&g_agg[(size_t)prev * HID + 2*c2 + 1], run1);
            }
        }
        __syncthreads();
    }
}

// ---------------- fused node update: HMMA, K=256 then K=128 (R14 config) ----------------
#define UT   67584
#define UW1  102400
#define UW2  169984
#define UMISC 204800
#define SMEM_UPD (UMISC + 1536)

__global__ __launch_bounds__(512, 1) void k_upd(float* __restrict__ h, const float* __restrict__ ub1,
                                                const float* __restrict__ ub2, int lvl){
    extern __shared__ char smc[];
    u32 smb = s2u(smc);
    int tid = threadIdx.x, wid = tid >> 5, lane = tid & 31;
    int*   snode = (int*)(smc + UMISC);
    float* b1s   = (float*)(smc + UMISC + 512);
    float* b2s   = (float*)(smc + UMISC + 1024);

    int cnt  = g_ncnt[lvl];
    int base = g_noff[lvl];
    int ntiles = (cnt + 127) >> 7;
    if ((int)blockIdx.x >= ntiles) return;

    for (int i = tid; i < 4096; i += 512){
        int n = i >> 5, kc = i & 31;
        *(uint4*)(smc + UW1 + (u32)n * 528 + (u32)kc * 16) = ((const uint4*)g_u1h)[i];
    }
    for (int i = tid; i < 2048; i += 512){
        int n = i >> 4, kc = i & 15;
        *(uint4*)(smc + UW2 + (u32)n * 272 + (u32)kc * 16) = ((const uint4*)g_u2h)[i];
    }
    if (tid < 128){ b1s[tid] = ub1[tid]; b2s[tid] = ub2[tid]; }
    __syncthreads();

    int rgrp = wid >> 1, nh = wid & 1;
    u32 afrag1 = smb + (u32)(rgrp * 16 + (lane & 15)) * 528 + (u32)((lane >> 4) << 4);
    u32 afrag2 = smb + UT + (u32)(rgrp * 16 + (lane & 15)) * 272 + (u32)((lane >> 4) << 4);
    int ra = rgrp * 16 + (lane >> 2);
    int rb = ra + 8;
    u32 lanemap1 = (u32)(((lane >> 4) << 3) + (lane & 7)) * 528 + (u32)(((lane >> 3) & 1) << 4);
    u32 lanemap2 = (u32)(((lane >> 4) << 3) + (lane & 7)) * 272 + (u32)(((lane >> 3) & 1) << 4);

    for (int t = blockIdx.x; t < ntiles; t += gridDim.x){
        __syncthreads();
        {
            int m = tid >> 2, q = tid & 3;
            int p = t * 128 + m;
            int v = (p < cnt) ? g_nperm[base + p] : 0;
            float inv = g_inv[v];
            if (q == 0) snode[m] = (p < cnt) ? v : -1;
            const uint4*  hr = (const uint4*)(&g_hf[(size_t)v * HID]);
            const float4* ar = (const float4*)(&g_agg[(size_t)v * HID]);
            #pragma unroll
            for (int j = 0; j < 4; ++j){
                int q4 = q * 4 + j;
                *(uint4*)(smc + (u32)m * 528 + (u32)q4 * 16) = hr[q4];
                float4 a0 = ar[2 * q4], a1 = ar[2 * q4 + 1];
                uint4 pv;
                pv.x = h2pack(a0.x * inv, a0.y * inv);
                pv.y = h2pack(a0.z * inv, a0.w * inv);
                pv.z = h2pack(a1.x * inv, a1.y * inv);
                pv.w = h2pack(a1.z * inv, a1.w * inv);
                *(uint4*)(smc + (u32)m * 528 + 256 + (u32)q4 * 16) = pv;
            }
        }
        __syncthreads();

        u32 a1[16][4];
        #pragma unroll
        for (int kc = 0; kc < 16; ++kc) LDX4(a1[kc], afrag1 + kc * 32);

        u32 w1b = smb + UW1 + (u32)(nh * 64) * 528 + lanemap1;
        #pragma unroll
        for (int np = 0; np < 4; ++np){
            float aH0[4] = {0,0,0,0}, aH1[4] = {0,0,0,0};
            u32 wb = w1b + (u32)np * 16 * 528;
            #pragma unroll
            for (int kc = 0; kc < 16; ++kc){
                u32 bh[4];
                LDX4(bh, wb + kc * 32);
                MMAH(aH0, a1[kc], bh[0], bh[1]);
                MMAH(aH1, a1[kc], bh[2], bh[3]);
            }
            #pragma unroll
            for (int nch = 0; nch < 2; ++nch){
                const float* H = nch ? aH1 : aH0;
                int c = nh * 64 + np * 16 + nch * 8 + 2 * (lane & 3);
                float bb0 = b1s[c], bb1 = b1s[c+1];
                float v0 = fmaxf(H[0] + bb0, 0.f);
                float v1 = fmaxf(H[1] + bb1, 0.f);
                *(u32*)(smc + UT + (u32)ra * 272 + (u32)c * 2) = h2pack(v0, v1);
                v0 = fmaxf(H[2] + bb0, 0.f);
                v1 = fmaxf(H[3] + bb1, 0.f);
                *(u32*)(smc + UT + (u32)rb * 272 + (u32)c * 2) = h2pack(v0, v1);
            }
        }
        PAIR_BAR(rgrp + 1);

        u32 a2[8][4];
        #pragma unroll
        for (int kc = 0; kc < 8; ++kc) LDX4(a2[kc], afrag2 + kc * 32);

        u32 w2b = smb + UW2 + (u32)(nh * 64) * 272 + lanemap2;
        int na = snode[ra], nb = snode[rb];
        #pragma unroll
        for (int np = 0; np < 4; ++np){
            float aH0[4] = {0,0,0,0}, aH1[4] = {0,0,0,0};
            u32 wb = w2b + (u32)np * 16 * 272;
            #pragma unroll
            for (int kc = 0; kc < 8; ++kc){
                u32 bh[4];
                LDX4(bh, wb + kc * 32);
                MMAH(aH0, a2[kc], bh[0], bh[1]);
                MMAH(aH1, a2[kc], bh[2], bh[3]);
            }
            #pragma unroll
            for (int nch = 0; nch < 2; ++nch){
                const float* H = nch ? aH1 : aH0;
                int c = nh * 64 + np * 16 + nch * 8 + 2 * (lane & 3);
                float bb0 = b2s[c], bb1 = b2s[c+1];
                float v0 = fmaxf(H[0] + bb0, 0.f);
                float v1 = fmaxf(H[1] + bb1, 0.f);
                if (na >= 0){
                    *(float2*)(h + (size_t)na * HID + c) = make_float2(v0, v1);
                    *(u32*)(&g_hf[(size_t)na * HID + c]) = h2pack(v0, v1);
                }
                v0 = fmaxf(H[2] + bb0, 0.f);
                v1 = fmaxf(H[3] + bb1, 0.f);
                if (nb >= 0){
                    *(float2*)(h + (size_t)nb * HID + c) = make_float2(v0, v1);
                    *(u32*)(&g_hf[(size_t)nb * HID + c]) = h2pack(v0, v1);
                }
            }
        }
    }
}

// ---------------- host launch ----------------
extern "C" void kernel_launch(void* const* d_in, const int* in_sizes, int n_in,
                              void* d_out, int out_size){
    const float* x     = (const float*)d_in[0];
    const int*   ei    = (const int*)  d_in[1];
    const float* eattr = (const float*)d_in[2];
    const int*   depth = (const int*)  d_in[3];
    const float* pw    = (const float*)d_in[4];
    const float* pb    = (const float*)d_in[5];
    const float* mw1   = (const float*)d_in[6];
    const float* mb1   = (const float*)d_in[7];
    const float* mw2   = (const float*)d_in[8];
    const float* mb2   = (const float*)d_in[9];
    const float* uw1   = (const float*)d_in[10];
    const float* ub1   = (const float*)d_in[11];
    const float* uw2   = (const float*)d_in[12];
    const float* ub2   = (const float*)d_in[13];
    float* h = (float*)d_out;

    int N = in_sizes[3];
    int E = in_sizes[2];

    static int sms = 0;
    if (sms == 0){
        cudaDeviceGetAttribute(&sms, cudaDevAttrMultiProcessorCount, 0);
        if (sms <= 0) sms = 148;
        cudaFuncSetAttribute(k_proj, cudaFuncAttributeMaxDynamicSharedMemorySize, SMEM_PROJ);
        cudaFuncSetAttribute(k_msg,  cudaFuncAttributeMaxDynamicSharedMemorySize, SMEM_MSG);
        cudaFuncSetAttribute(k_upd,  cudaFuncAttributeMaxDynamicSharedMemorySize, SMEM_UPD);
    }

    k_init<<<1024, 256>>>(N * HID, N, mw1, mw2, uw1, uw2, pw);

    int mx = (E > N) ? E : N;
    k_count<<<(mx + 255) / 256, 256>>>(ei, depth, N, E);
    k_snodes<<<(N + 255) / 256, 256>>>(depth, N);
    k_sedges<<<(E + 255) / 256, 256>>>(ei, eattr, E);

    k_proj<<<2 * sms, 256, SMEM_PROJ>>>(x, pb, h, N);

    for (int d = 1; d <= 4; ++d){
        k_msg<<<2 * sms, 512, SMEM_MSG>>>(mw1, mb1, mb2, d);
        k_upd<<<sms, 512, SMEM_UPD>>>(h, ub1, ub2, d);
    }
}